// round 1
// baseline (speedup 1.0000x reference)
#include <cuda_runtime.h>
#include <math.h>

#define Bsz 4
#define Nq  8192
#define Mp  2048
#define C1  128
#define C2  256
#define CIN 384
#define CO0 256
#define CO1 128
#define NC  (Bsz*Nq)   // 32768

// ---------------- scratch (static device globals; no allocation) ----------------
__device__ float g_p2T[Bsz*Mp*C2];            // points2 transposed (B,M,C2)   8 MB
__device__ float g_X[(size_t)NC*CIN];         // concat input, layout [col][k] 50 MB
__device__ float g_Y0[(size_t)CO0*NC];        // conv0 raw output [o][col]     33 MB
__device__ float g_scale0[CO0], g_shift0[CO0];
__device__ float g_scale1[CO1], g_shift1[CO1];

// ---------------- transpose: in (B,R,C) -> out[(b*C+c)*ostride + ooff + r] ------
__global__ void transpose_kernel(const float* __restrict__ in, float* __restrict__ out,
                                 int R, int C, int ostride, int ooff)
{
    __shared__ float tile[32][33];
    int b  = blockIdx.z;
    int c0 = blockIdx.x * 32;
    int r0 = blockIdx.y * 32;
    const float* ip = in + (size_t)b * R * C;
#pragma unroll
    for (int s = 0; s < 4; s++) {
        int r = r0 + threadIdx.y + 8*s;
        tile[threadIdx.y + 8*s][threadIdx.x] = ip[(size_t)r * C + c0 + threadIdx.x];
    }
    __syncthreads();
#pragma unroll
    for (int s = 0; s < 4; s++) {
        int c = c0 + threadIdx.y + 8*s;
        out[((size_t)b * C + c) * ostride + ooff + r0 + threadIdx.x] = tile[threadIdx.x][threadIdx.y + 8*s];
    }
}

// ---------------- 3-NN + weights + interpolation -> g_X[col][0..255] -----------
__global__ __launch_bounds__(128) void knn_interp_kernel(
    const float* __restrict__ xyz1, const float* __restrict__ xyz2,
    const float* __restrict__ norm1, const float* __restrict__ norm2)
{
    __shared__ float4 sp[Mp];   // {px, py, pz, pp}  32 KB
    int b = blockIdx.y;
    const float* x2 = xyz2 + (size_t)b * 3 * Mp;
    for (int m = threadIdx.x; m < Mp; m += 128) {
        float a = x2[m], c = x2[Mp + m], d = x2[2*Mp + m];
        float4 v; v.x = a; v.y = c; v.z = d; v.w = a*a + c*c + d*d;
        sp[m] = v;
    }
    __syncthreads();

    int n = blockIdx.x * 128 + threadIdx.x;
    const float* x1 = xyz1 + (size_t)b * 3 * Nq;
    float qx = x1[n], qy = x1[Nq + n], qz = x1[2*Nq + n];
    float qq = qx*qx + qy*qy + qz*qz;

    float d2_0 = 1e30f, d2_1 = 1e30f, d2_2 = 1e30f;
    int   i0 = 0, i1 = 0, i2 = 0;
#pragma unroll 4
    for (int m = 0; m < Mp; m++) {
        float4 P = sp[m];
        float dot = qx*P.x + qy*P.y + qz*P.z;
        float d2  = qq + P.w - 2.0f*dot;          // matches reference's expanded form
        if (d2 < d2_2) {                           // strict < : ties keep lower index
            if (d2 < d2_1) {
                d2_2 = d2_1; i2 = i1;
                if (d2 < d2_0) { d2_1 = d2_0; i1 = i0; d2_0 = d2; i0 = m; }
                else           { d2_1 = d2;  i1 = m; }
            } else { d2_2 = d2; i2 = m; }
        }
    }
    float dist0 = sqrtf(fmaxf(d2_0, 1e-20f));
    float dist1 = sqrtf(fmaxf(d2_1, 1e-20f));
    float dist2 = sqrtf(fmaxf(d2_2, 1e-20f));

    const float* n1 = norm1 + (size_t)b * 3 * Nq;
    const float* n2 = norm2 + (size_t)b * 3 * Mp;
    float ax = n1[n], ay = n1[Nq+n], az = n1[2*Nq+n];
    float dx, dy, dz;
    dx = ax - n2[i0]; dy = ay - n2[Mp+i0]; dz = az - n2[2*Mp+i0];
    float nd0 = sqrtf(dx*dx + dy*dy + dz*dz);
    dx = ax - n2[i1]; dy = ay - n2[Mp+i1]; dz = az - n2[2*Mp+i1];
    float nd1 = sqrtf(dx*dx + dy*dy + dz*dz);
    dx = ax - n2[i2]; dy = ay - n2[Mp+i2]; dz = az - n2[2*Mp+i2];
    float nd2 = sqrtf(dx*dx + dy*dy + dz*dz);

    float r0 = 1.0f / fmaxf(dist0, 1e-10f);
    float r1 = 1.0f / fmaxf(dist1, 1e-10f);
    float r2 = 1.0f / fmaxf(dist2, 1e-10f);
    float rs = r0 + r1 + r2;
    float s0 = 1.0f / fmaxf(nd0, 1e-10f);
    float s1 = 1.0f / fmaxf(nd1, 1e-10f);
    float s2 = 1.0f / fmaxf(nd2, 1e-10f);
    float ssum = s0 + s1 + s2;
    float w0 = (r0 / rs) * (s0 / ssum);
    float w1 = (r1 / rs) * (s1 / ssum);
    float w2 = (r2 / rs) * (s2 / ssum);

    size_t col = (size_t)b * Nq + n;
    const float4* p0 = (const float4*)(g_p2T + ((size_t)b*Mp + i0) * C2);
    const float4* p1 = (const float4*)(g_p2T + ((size_t)b*Mp + i1) * C2);
    const float4* p2 = (const float4*)(g_p2T + ((size_t)b*Mp + i2) * C2);
    float4* xo = (float4*)(g_X + col * CIN);
#pragma unroll 4
    for (int c = 0; c < C2/4; c++) {
        float4 a = p0[c], bq = p1[c], cq = p2[c];
        float4 r;
        r.x = w0*a.x + w1*bq.x + w2*cq.x;
        r.y = w0*a.y + w1*bq.y + w2*cq.y;
        r.z = w0*a.z + w1*bq.z + w2*cq.z;
        r.w = w0*a.w + w1*bq.w + w2*cq.w;
        xo[c] = r;
    }
}

// ---------------- GEMM0: Y0[o][col] = W0(256x384) @ X^T + b0 -------------------
// A = W0 row-major; B[k][col] = g_X[col*384 + k]
__global__ __launch_bounds__(256) void gemm0_kernel(const float* __restrict__ A,
                                                    const float* __restrict__ bias)
{
    __shared__ float As[128*16];   // [row][k], stride 16
    __shared__ float Bs[16*132];   // [k][col], stride 132 (16B-aligned rows)
    int t  = threadIdx.x;
    int c0 = blockIdx.x * 128;
    int m0 = blockIdx.y * 128;
    int tx = t & 15, ty = t >> 4;
    float acc[8][8] = {};

    for (int kk = 0; kk < CIN; kk += 16) {
        if (t < 128) {
            const float* ap = A + (size_t)(m0 + t) * CIN + kk;
            float4 v0 = *(const float4*)(ap);
            float4 v1 = *(const float4*)(ap+4);
            float4 v2 = *(const float4*)(ap+8);
            float4 v3 = *(const float4*)(ap+12);
            float4* as = (float4*)&As[t*16];
            as[0]=v0; as[1]=v1; as[2]=v2; as[3]=v3;
        } else {
            int colv = t - 128;
            const float* xp = g_X + (size_t)(c0 + colv) * CIN + kk;
            float4 v0 = *(const float4*)(xp);
            float4 v1 = *(const float4*)(xp+4);
            float4 v2 = *(const float4*)(xp+8);
            float4 v3 = *(const float4*)(xp+12);
            Bs[ 0*132+colv]=v0.x; Bs[ 1*132+colv]=v0.y; Bs[ 2*132+colv]=v0.z; Bs[ 3*132+colv]=v0.w;
            Bs[ 4*132+colv]=v1.x; Bs[ 5*132+colv]=v1.y; Bs[ 6*132+colv]=v1.z; Bs[ 7*132+colv]=v1.w;
            Bs[ 8*132+colv]=v2.x; Bs[ 9*132+colv]=v2.y; Bs[10*132+colv]=v2.z; Bs[11*132+colv]=v2.w;
            Bs[12*132+colv]=v3.x; Bs[13*132+colv]=v3.y; Bs[14*132+colv]=v3.z; Bs[15*132+colv]=v3.w;
        }
        __syncthreads();
#pragma unroll
        for (int k = 0; k < 16; k++) {
            float av[8], bv[8];
#pragma unroll
            for (int i = 0; i < 8; i++) av[i] = As[(ty*8+i)*16 + k];
            float4 pb = *(const float4*)&Bs[k*132 + tx*8];
            float4 qb = *(const float4*)&Bs[k*132 + tx*8 + 4];
            bv[0]=pb.x; bv[1]=pb.y; bv[2]=pb.z; bv[3]=pb.w;
            bv[4]=qb.x; bv[5]=qb.y; bv[6]=qb.z; bv[7]=qb.w;
#pragma unroll
            for (int i = 0; i < 8; i++)
#pragma unroll
                for (int j = 0; j < 8; j++)
                    acc[i][j] = fmaf(av[i], bv[j], acc[i][j]);
        }
        __syncthreads();
    }
#pragma unroll
    for (int i = 0; i < 8; i++) {
        int m = m0 + ty*8 + i;
        float bi = bias[m];
        float4 o0, o1;
        o0.x = acc[i][0]+bi; o0.y = acc[i][1]+bi; o0.z = acc[i][2]+bi; o0.w = acc[i][3]+bi;
        o1.x = acc[i][4]+bi; o1.y = acc[i][5]+bi; o1.z = acc[i][6]+bi; o1.w = acc[i][7]+bi;
        float* yp = g_Y0 + (size_t)m * NC + c0 + tx*8;
        *(float4*)yp = o0; *(float4*)(yp+4) = o1;
    }
}

// ---------------- GEMM1: out_raw[b][o][n] = W1 @ relu(bn0(Y0)) + b1 -------------
__global__ __launch_bounds__(256) void gemm1_kernel(const float* __restrict__ A,
                                                    const float* __restrict__ bias,
                                                    float* __restrict__ out)
{
    __shared__ float As[128*16];
    __shared__ float Bs[16*132];
    int t  = threadIdx.x;
    int c0 = blockIdx.x * 128;
    int tx = t & 15, ty = t >> 4;
    float acc[8][8] = {};

    for (int kk = 0; kk < CO0; kk += 16) {
        if (t < 128) {
            const float* ap = A + (size_t)t * CO0 + kk;
            float4 v0 = *(const float4*)(ap);
            float4 v1 = *(const float4*)(ap+4);
            float4 v2 = *(const float4*)(ap+8);
            float4 v3 = *(const float4*)(ap+12);
            float4* as = (float4*)&As[t*16];
            as[0]=v0; as[1]=v1; as[2]=v2; as[3]=v3;
        } else {
            int u = t - 128;
            int k = u >> 3;             // 0..15
            int colq = (u & 7) * 16;    // 0..112
            float sc = g_scale0[kk + k];
            float sh = g_shift0[kk + k];
            const float* yp = g_Y0 + (size_t)(kk + k) * NC + c0 + colq;
#pragma unroll
            for (int q = 0; q < 4; q++) {
                float4 v = *(const float4*)(yp + 4*q);
                v.x = fmaxf(0.f, fmaf(v.x, sc, sh));
                v.y = fmaxf(0.f, fmaf(v.y, sc, sh));
                v.z = fmaxf(0.f, fmaf(v.z, sc, sh));
                v.w = fmaxf(0.f, fmaf(v.w, sc, sh));
                *(float4*)&Bs[k*132 + colq + 4*q] = v;
            }
        }
        __syncthreads();
#pragma unroll
        for (int k = 0; k < 16; k++) {
            float av[8], bv[8];
#pragma unroll
            for (int i = 0; i < 8; i++) av[i] = As[(ty*8+i)*16 + k];
            float4 pb = *(const float4*)&Bs[k*132 + tx*8];
            float4 qb = *(const float4*)&Bs[k*132 + tx*8 + 4];
            bv[0]=pb.x; bv[1]=pb.y; bv[2]=pb.z; bv[3]=pb.w;
            bv[4]=qb.x; bv[5]=qb.y; bv[6]=qb.z; bv[7]=qb.w;
#pragma unroll
            for (int i = 0; i < 8; i++)
#pragma unroll
                for (int j = 0; j < 8; j++)
                    acc[i][j] = fmaf(av[i], bv[j], acc[i][j]);
        }
        __syncthreads();
    }
    int bidx  = c0 >> 13;          // batch (column tile never crosses batch)
    int nbase = c0 & (Nq - 1);
#pragma unroll
    for (int i = 0; i < 8; i++) {
        int m = ty*8 + i;
        float bi = bias[m];
        float4 o0, o1;
        o0.x = acc[i][0]+bi; o0.y = acc[i][1]+bi; o0.z = acc[i][2]+bi; o0.w = acc[i][3]+bi;
        o1.x = acc[i][4]+bi; o1.y = acc[i][5]+bi; o1.z = acc[i][6]+bi; o1.w = acc[i][7]+bi;
        float* op = out + (size_t)bidx * (CO1*Nq) + (size_t)m * Nq + nbase + tx*8;
        *(float4*)op = o0; *(float4*)(op+4) = o1;
    }
}

// ---------------- per-channel BN stats (deterministic, no atomics) --------------
__global__ __launch_bounds__(256) void stats_kernel(const float* __restrict__ Y,
    const float* __restrict__ g, const float* __restrict__ be,
    float* __restrict__ scale, float* __restrict__ shift,
    long long chan_stride, int nchunks, long long chunk_stride, int chunk_len, float inv_count)
{
    int o = blockIdx.x;
    int tid = threadIdx.x;
    double s = 0.0, q = 0.0;
    for (int cb = 0; cb < nchunks; cb++) {
        const float* p = Y + (size_t)o * chan_stride + (size_t)cb * chunk_stride;
        for (int i = tid; i < chunk_len; i += 256) {
            double v = (double)p[i];
            s += v; q += v*v;
        }
    }
    __shared__ double ss[256], sq[256];
    ss[tid] = s; sq[tid] = q;
    __syncthreads();
    for (int st = 128; st > 0; st >>= 1) {
        if (tid < st) { ss[tid] += ss[tid+st]; sq[tid] += sq[tid+st]; }
        __syncthreads();
    }
    if (tid == 0) {
        double mean = ss[0] * (double)inv_count;
        double var  = sq[0] * (double)inv_count - mean*mean;
        double sc   = (double)g[o] / sqrt(var + 1e-5);
        scale[o] = (float)sc;
        shift[o] = (float)((double)be[o] - mean * sc);
    }
}

// ---------------- final BN + ReLU, in place on d_out ----------------------------
__global__ __launch_bounds__(256) void bnrelu_kernel(float* __restrict__ out)
{
    int i = blockIdx.x * 256 + threadIdx.x;   // float4 index; total 1048576
    int o = (i >> 11) & 127;
    float sc = g_scale1[o], sh = g_shift1[o];
    float4* p = (float4*)out;
    float4 v = p[i];
    v.x = fmaxf(0.f, fmaf(v.x, sc, sh));
    v.y = fmaxf(0.f, fmaf(v.y, sc, sh));
    v.z = fmaxf(0.f, fmaf(v.z, sc, sh));
    v.w = fmaxf(0.f, fmaf(v.w, sc, sh));
    p[i] = v;
}

// ---------------- launch ---------------------------------------------------------
extern "C" void kernel_launch(void* const* d_in, const int* in_sizes, int n_in,
                              void* d_out, int out_size)
{
    const float* xyz1    = (const float*)d_in[0];
    const float* xyz2    = (const float*)d_in[1];
    const float* norm1   = (const float*)d_in[2];
    const float* norm2   = (const float*)d_in[3];
    const float* points1 = (const float*)d_in[4];
    const float* points2 = (const float*)d_in[5];
    const float* W0      = (const float*)d_in[6];
    const float* b0      = (const float*)d_in[7];
    const float* g0      = (const float*)d_in[8];
    const float* be0     = (const float*)d_in[9];
    const float* W1      = (const float*)d_in[10];
    const float* b1      = (const float*)d_in[11];
    const float* g1      = (const float*)d_in[12];
    const float* be1     = (const float*)d_in[13];
    float* out = (float*)d_out;

    float *p2T_ptr, *X_ptr, *Y0_ptr, *sc0, *sh0, *sc1, *sh1;
    cudaGetSymbolAddress((void**)&p2T_ptr, g_p2T);
    cudaGetSymbolAddress((void**)&X_ptr,   g_X);
    cudaGetSymbolAddress((void**)&Y0_ptr,  g_Y0);
    cudaGetSymbolAddress((void**)&sc0, g_scale0);
    cudaGetSymbolAddress((void**)&sh0, g_shift0);
    cudaGetSymbolAddress((void**)&sc1, g_scale1);
    cudaGetSymbolAddress((void**)&sh1, g_shift1);

    // points2 (B,256,2048) -> g_p2T (B,2048,256)
    transpose_kernel<<<dim3(Mp/32, C2/32, Bsz), dim3(32,8)>>>(points2, p2T_ptr, C2, Mp, C2, 0);
    // points1 (B,128,8192) -> g_X[col][256..383]
    transpose_kernel<<<dim3(Nq/32, C1/32, Bsz), dim3(32,8)>>>(points1, X_ptr, C1, Nq, CIN, C2);
    // 3-NN + weights + interpolation -> g_X[col][0..255]
    knn_interp_kernel<<<dim3(Nq/128, Bsz), 128>>>(xyz1, xyz2, norm1, norm2);
    // conv0 raw
    gemm0_kernel<<<dim3(NC/128, CO0/128), 256>>>(W0, b0);
    // bn0 stats
    stats_kernel<<<CO0, 256>>>(Y0_ptr, g0, be0, sc0, sh0,
                               (long long)NC, 1, 0LL, NC, 1.0f/(float)NC);
    // conv1 raw (bn0 + relu fused on load), write raw to d_out
    gemm1_kernel<<<dim3(NC/128, 1), 256>>>(W1, b1, out);
    // bn1 stats over d_out raw
    stats_kernel<<<CO1, 256>>>(out, g1, be1, sc1, sh1,
                               (long long)Nq, Bsz, (long long)(CO1*Nq), Nq, 1.0f/(float)NC);
    // final bn1 + relu, in place
    bnrelu_kernel<<<(Bsz*CO1*Nq/4)/256, 256>>>(out);
}